// round 13
// baseline (speedup 1.0000x reference)
#include <cuda_runtime.h>

#define Bb 2
#define Ss 2048
#define Hh 1024
#define HEADS 16
#define KD 64
#define VD 2048
#define HD 128
#define MS (Bb*Ss)   /* 4096 rows */

// ---------------- scratch (device globals; no allocation allowed) ----------
__device__ float g_q [MS*Hh];
__device__ float g_k [MS*Hh];
__device__ float g_v [MS*VD];
__device__ float g_g [MS*VD];
__device__ float g_ao[MS*VD];
__device__ float g_xr[MS*Hh];          // tf32-rounded x
__device__ float g_wr[8*1024*1024];    // tf32-rounded Wq|Wk|Wv|Wg|Wo
__device__ float g_vt[MS*VD];          // V transposed: [bh][n][t]

// ---------------- helpers --------------------------------------------------
__device__ __forceinline__ float to_tf32(float x) {
    unsigned u;
    asm("cvt.rna.tf32.f32 %0, %1;" : "=r"(u) : "f"(x));
    return __uint_as_float(u);
}

#define MMA_TF32(c, a, b)                                                     \
    asm volatile(                                                             \
        "mma.sync.aligned.m16n8k8.row.col.f32.tf32.tf32.f32 "                 \
        "{%0,%1,%2,%3}, {%4,%5,%6,%7}, {%8,%9}, {%0,%1,%2,%3};"               \
        : "+f"((c)[0]), "+f"((c)[1]), "+f"((c)[2]), "+f"((c)[3])              \
        : "r"((a)[0]), "r"((a)[1]), "r"((a)[2]), "r"((a)[3]),                 \
          "r"((b)[0]), "r"((b)[1]))

__device__ __forceinline__ void ldsm4(unsigned r[4], unsigned addr) {
    asm volatile("ldmatrix.sync.aligned.m8n8.x4.shared.b16 {%0,%1,%2,%3}, [%4];"
                 : "=r"(r[0]), "=r"(r[1]), "=r"(r[2]), "=r"(r[3]) : "r"(addr));
}
__device__ __forceinline__ void cp16(unsigned saddr, const void* gaddr) {
    asm volatile("cp.async.cg.shared.global [%0], [%1], 16;"
                 :: "r"(saddr), "l"(gaddr));
}
#define CP_COMMIT() asm volatile("cp.async.commit_group;")
#define CP_WAIT1()  asm volatile("cp.async.wait_group 1;")
#define CP_WAIT0()  asm volatile("cp.async.wait_group 0;")

// ---------------- producer-side tf32 rounding pass --------------------------
__global__ __launch_bounds__(256)
void pre_round(const float4* __restrict__ x,  const float4* __restrict__ wq,
               const float4* __restrict__ wk, const float4* __restrict__ wv,
               const float4* __restrict__ wg, const float4* __restrict__ wo,
               float4* __restrict__ xr, float4* __restrict__ wr)
{
    int i = blockIdx.x * blockDim.x + threadIdx.x;
    const float4* src; float4* dst; int off;
    if (i < 1048576)      { src = x;  dst = xr;            off = i; }
    else if (i < 1310720) { src = wq; dst = wr;            off = i - 1048576; }
    else if (i < 1572864) { src = wk; dst = wr + 262144;   off = i - 1310720; }
    else if (i < 2097152) { src = wv; dst = wr + 524288;   off = i - 1572864; }
    else if (i < 2621440) { src = wg; dst = wr + 1048576;  off = i - 2097152; }
    else                  { src = wo; dst = wr + 1572864;  off = i - 2621440; }
    float4 a = src[off];
    dst[off] = make_float4(to_tf32(a.x), to_tf32(a.y), to_tf32(a.z), to_tf32(a.w));
}

// ---------------- V transpose: v[b*Ss+t][h*HD+n] -> vt[bh*HD+n][t] ---------
__global__ __launch_bounds__(256)
void transpose_v(const float* __restrict__ v, float* __restrict__ vt)
{
    __shared__ float tile[32][33];
    const int tx = threadIdx.x, ty = threadIdx.y;       // 32 x 8
    const int t0 = blockIdx.x * 32, n0 = blockIdx.y * 32, bh = blockIdx.z;
    const int b = bh >> 4, h = bh & 15;
#pragma unroll
    for (int j = 0; j < 4; j++)
        tile[ty + j * 8][tx] =
            v[(size_t)(b * Ss + t0 + ty + j * 8) * VD + h * HD + n0 + tx];
    __syncthreads();
#pragma unroll
    for (int j = 0; j < 4; j++)
        vt[((size_t)bh * HD + n0 + ty + j * 8) * Ss + t0 + tx] =
            tile[tx][ty + j * 8];
}

// ============================================================================
// Core 128x128 tf32 GEMM body (unchanged from R11, proven).
// ============================================================================
__device__ __forceinline__ void gemm128_body(
    const float* __restrict__ A, const float* __restrict__ Bm,
    float* __restrict__ C, int N, int K, float alpha,
    int m0, int n0, bool rope, bool outRound,
    const float* __restrict__ sn, const float* __restrict__ cs,
    float* As, float* Bs)
{
    const int tid  = threadIdx.x;
    const int warp = tid >> 5, lane = tid & 31;
    const int g    = lane >> 2, t = lane & 3;
    const int wm   = warp >> 1;
    const int wn   = warp & 1;
    const int row0 = tid >> 2;
    const int k4   = tid & 3;

    float acc[4][8][4];
#pragma unroll
    for (int i = 0; i < 4; i++)
#pragma unroll
        for (int j = 0; j < 8; j++)
#pragma unroll
            for (int r = 0; r < 4; r++) acc[i][j][r] = 0.f;

    const float* Ag = A  + (size_t)(m0 + row0) * K + k4 * 4;
    const float* Bg = Bm + (size_t)(n0 + row0) * K + k4 * 4;
    const size_t rstep = (size_t)32 * K;

    const unsigned aSb = (unsigned)__cvta_generic_to_shared(As);
    const unsigned bSb = (unsigned)__cvta_generic_to_shared(Bs);

    unsigned sA[4], sB[4];
#pragma unroll
    for (int r = 0; r < 4; r++) {
        int rr  = row0 + r * 32;
        int idx = rr * 4 + (k4 ^ ((rr >> 1) & 3));
        sA[r] = aSb + idx * 16;
        sB[r] = bSb + idx * 16;
    }

    const int sel = lane >> 3;
    unsigned a_off[4]; int a_sw[4];
#pragma unroll
    for (int mi = 0; mi < 4; mi++) {
        int mr = wm * 64 + mi * 16 + (sel & 1) * 8 + (lane & 7);
        a_sw[mi]  = (mr >> 1) & 3;
        a_off[mi] = aSb + mr * 64;
    }
    const int dkA = sel >> 1;
    unsigned b_off[4]; int b_sw[4];
#pragma unroll
    for (int p = 0; p < 4; p++) {
        int nr = wn * 64 + p * 16 + (sel >> 1) * 8 + (lane & 7);
        b_sw[p]  = (nr >> 1) & 3;
        b_off[p] = bSb + nr * 64;
    }
    const int dkB = sel & 1;

    const int NIT = K / 16;

#pragma unroll
    for (int st = 0; st < 2; st++) {
        const float* Agn = Ag + st * 16;
        const float* Bgn = Bg + st * 16;
#pragma unroll
        for (int r = 0; r < 4; r++) {
            cp16(sA[r] + st * 8192, Agn + r * rstep);
            cp16(sB[r] + st * 8192, Bgn + r * rstep);
        }
        CP_COMMIT();
    }

    int stage = 0;
    for (int it = 0; it < NIT; ++it) {
        CP_WAIT1();
        __syncthreads();

        const int inext = it + 2;
        if (inext < NIT) {
            const unsigned so = (unsigned)((inext % 3) * 8192);
            const float* Agn = Ag + inext * 16;
            const float* Bgn = Bg + inext * 16;
#pragma unroll
            for (int r = 0; r < 4; r++) {
                cp16(sA[r] + so, Agn + r * rstep);
                cp16(sB[r] + so, Bgn + r * rstep);
            }
        }
        CP_COMMIT();

        const unsigned so = (unsigned)(stage * 8192);
#pragma unroll
        for (int ks = 0; ks < 2; ks++) {
            const int ks2 = ks * 2;
            unsigned af[4][4];
#pragma unroll
            for (int mi = 0; mi < 4; mi++)
                ldsm4(af[mi], a_off[mi] + so + (((ks2 + dkA) ^ a_sw[mi]) << 4));
            unsigned bf[4][4];
#pragma unroll
            for (int p = 0; p < 4; p++)
                ldsm4(bf[p], b_off[p] + so + (((ks2 + dkB) ^ b_sw[p]) << 4));
#pragma unroll
            for (int mi = 0; mi < 4; mi++)
#pragma unroll
                for (int nj = 0; nj < 8; nj++)
                    MMA_TF32(acc[mi][nj], af[mi], &bf[nj >> 1][(nj & 1) * 2]);
        }
        stage = (stage == 2) ? 0 : stage + 1;
    }

#pragma unroll
    for (int mi = 0; mi < 4; mi++) {
        int r0  = m0 + wm * 64 + mi * 16 + g;
        int sA_ = r0 & (Ss - 1);
        int sB_ = (r0 + 8) & (Ss - 1);
#pragma unroll
        for (int nj = 0; nj < 8; nj++) {
            int col = n0 + wn * 64 + nj * 8 + 2 * t;
            float e0 = alpha * acc[mi][nj][0];
            float o0 = alpha * acc[mi][nj][1];
            float e1 = alpha * acc[mi][nj][2];
            float o1 = alpha * acc[mi][nj][3];
            if (rope) {
                int hc = col & 63;
                float2 cA = *(const float2*)&cs[sA_ * KD + hc];
                float2 sAv= *(const float2*)&sn[sA_ * KD + hc];
                float2 cB = *(const float2*)&cs[sB_ * KD + hc];
                float2 sBv= *(const float2*)&sn[sB_ * KD + hc];
                float ne0 = e0 * cA.x - o0 * sAv.x;
                float no0 = o0 * cA.y + e0 * sAv.y;
                float ne1 = e1 * cB.x - o1 * sBv.x;
                float no1 = o1 * cB.y + e1 * sBv.y;
                e0 = ne0; o0 = no0; e1 = ne1; o1 = no1;
            }
            if (outRound) {
                e0 = to_tf32(e0); o0 = to_tf32(o0);
                e1 = to_tf32(e1); o1 = to_tf32(o1);
            }
            float2 w01 = { e0, o0 };
            float2 w23 = { e1, o1 };
            *(float2*)&C[(size_t)r0 * N + col]       = w01;
            *(float2*)&C[(size_t)(r0 + 8) * N + col] = w23;
        }
    }
}

// ---------------- fused Q/K/V/G projections (+rope on q,k) -----------------
__global__ __launch_bounds__(128, 2)
void proj_qkvg(const float* __restrict__ x, const float* __restrict__ wr,
               const float* __restrict__ sn, const float* __restrict__ cs,
               float* __restrict__ q, float* __restrict__ k,
               float* __restrict__ v, float* __restrict__ g)
{
    __shared__ float As[3 * 2048];
    __shared__ float Bs[3 * 2048];
    const int bx = blockIdx.x;
    const float* Bm; float* Cp; int Nloc; float alpha; bool rope, orn; int nb;
    if (bx < 8)       { Bm = wr;           Cp = q; Nloc = 1024; alpha = 1.f;    rope = true;  orn = true;  nb = bx; }
    else if (bx < 16) { Bm = wr + 1048576; Cp = k; Nloc = 1024; alpha = 0.125f; rope = true;  orn = true;  nb = bx - 8; }
    else if (bx < 32) { Bm = wr + 2097152; Cp = v; Nloc = 2048; alpha = 1.f;    rope = false; orn = true;  nb = bx - 16; }
    else              { Bm = wr + 4194304; Cp = g; Nloc = 2048; alpha = 1.f;    rope = false; orn = false; nb = bx - 32; }
    gemm128_body(x, Bm, Cp, Nloc, Hh, alpha, blockIdx.y * 128, nb * 128,
                 rope, orn, sn, cs, As, Bs);
}

// ---------------- output projection ----------------------------------------
__global__ __launch_bounds__(128, 2)
void gemm_out(const float* __restrict__ A, const float* __restrict__ Bm,
              float* __restrict__ C)
{
    __shared__ float As[3 * 2048];
    __shared__ float Bs[3 * 2048];
    gemm128_body(A, Bm, C, Hh, VD, 1.f, blockIdx.y * 128, blockIdx.x * 128,
                 false, false, nullptr, nullptr, As, Bs);
}

// ---------------- retention attention v2: ldmatrix + cp.async --------------
// 128 thr / 4 warps. Block tile: 64 q-rows. Warp tiles: S 32x32, O 32x64.
// Smem (floats): Qs[0,4096) Ks[4096,8192) Ssm[8192,12288) Vs[12288,20480)
//                part[20480,20608) rsum[20608,20672)
// All operand tiles use the GEMM chunk-XOR layout; fills via cp.async;
// fragments via ldmatrix.x4. V comes pre-transposed (vt[bh][n][t]).
__global__ __launch_bounds__(128, 2)
void attn_tc(const float* __restrict__ q, const float* __restrict__ k,
             const float* __restrict__ vt, const float* __restrict__ mask,
             const float* __restrict__ gate, float* __restrict__ ao)
{
    extern __shared__ float sm[];
    float* Ssm  = sm + 8192;
    float* part = sm + 20480;
    float* rsum = sm + 20608;

    const int tid  = threadIdx.x;
    const int warp = tid >> 5, lane = tid & 31;
    const int g    = lane >> 2, t = lane & 3;
    const int wm   = warp >> 1, wn = warp & 1;
    const int sb   = blockIdx.x, bh = blockIdx.y;
    const int b    = bh >> 4, h = bh & 15;
    const int s0   = sb * 64;
    const int sel  = lane >> 3;

    const unsigned qSb = (unsigned)__cvta_generic_to_shared(sm);
    const unsigned kSb = qSb + 16384;
    const unsigned sSb = qSb + 32768;
    const unsigned vSb = qSb + 49152;

    if (tid < 64) rsum[tid] = 0.f;

    // ldsm lane offsets (bytes, region-relative)
    unsigned a_off[2]; int a_sw[2];
#pragma unroll
    for (int mi = 0; mi < 2; mi++) {
        int mr = wm * 32 + mi * 16 + (sel & 1) * 8 + (lane & 7);
        a_sw[mi]  = (mr >> 1) & 3;
        a_off[mi] = mr * 64;
    }
    const int dkA = sel >> 1;
    unsigned bk_off[2]; int bk_sw[2];
#pragma unroll
    for (int p = 0; p < 2; p++) {
        int nr = wn * 32 + p * 16 + (sel >> 1) * 8 + (lane & 7);
        bk_sw[p]  = (nr >> 1) & 3;
        bk_off[p] = nr * 64;
    }
    unsigned bv_off[4]; int bv_sw[4];
#pragma unroll
    for (int p = 0; p < 4; p++) {
        int nr = wn * 64 + p * 16 + (sel >> 1) * 8 + (lane & 7);
        bv_sw[p]  = (nr >> 1) & 3;
        bv_off[p] = nr * 64;
    }
    const int dkB = sel & 1;

    // Q fill (once)
#pragma unroll
    for (int kb = 0; kb < 4; kb++)
#pragma unroll
        for (int i = 0; i < 2; i++) {
            int lin = tid + i * 128, rr = lin >> 2, c = lin & 3;
            cp16(qSb + kb * 4096 + (rr * 4 + (c ^ ((rr >> 1) & 3))) * 16,
                 q + (size_t)(b * Ss + s0 + rr) * Hh + h * KD + kb * 16 + c * 4);
        }
    CP_COMMIT();

    float oacc[2][8][4];
#pragma unroll
    for (int mi = 0; mi < 2; mi++)
#pragma unroll
        for (int nj = 0; nj < 8; nj++)
#pragma unroll
            for (int r = 0; r < 4; r++) oacc[mi][nj][r] = 0.f;

    const size_t mbase = (size_t)h * Ss * Ss;

    for (int tt = 0; tt <= sb; tt++) {
        const int t0 = tt * 64;

        // K + V fills
#pragma unroll
        for (int kb = 0; kb < 4; kb++) {
#pragma unroll
            for (int i = 0; i < 2; i++) {
                int lin = tid + i * 128, rr = lin >> 2, c = lin & 3;
                cp16(kSb + kb * 4096 + (rr * 4 + (c ^ ((rr >> 1) & 3))) * 16,
                     k + (size_t)(b * Ss + t0 + rr) * Hh + h * KD + kb * 16 + c * 4);
            }
#pragma unroll
            for (int i = 0; i < 4; i++) {
                int lin = tid + i * 128, nn = lin >> 2, c = lin & 3;
                cp16(vSb + kb * 8192 + (nn * 4 + (c ^ ((nn >> 1) & 3))) * 16,
                     vt + ((size_t)bh * HD + nn) * Ss + t0 + kb * 16 + c * 4);
            }
        }
        CP_COMMIT();
        CP_WAIT0();
        __syncthreads();

        // ---- S = Q * K^T -------------------------------------------------
        float sacc[2][4][4];
#pragma unroll
        for (int mi = 0; mi < 2; mi++)
#pragma unroll
            for (int nj = 0; nj < 4; nj++)
#pragma unroll
                for (int r = 0; r < 4; r++) sacc[mi][nj][r] = 0.f;

#pragma unroll
        for (int kb = 0; kb < 4; kb++)
#pragma unroll
            for (int ks = 0; ks < 2; ks++) {
                const int ks2 = ks * 2;
                unsigned af[2][4];
#pragma unroll
                for (int mi = 0; mi < 2; mi++)
                    ldsm4(af[mi], qSb + kb * 4096 + a_off[mi] +
                                  (((ks2 + dkA) ^ a_sw[mi]) << 4));
                unsigned bf[2][4];
#pragma unroll
                for (int p = 0; p < 2; p++)
                    ldsm4(bf[p], kSb + kb * 4096 + bk_off[p] +
                                 (((ks2 + dkB) ^ bk_sw[p]) << 4));
#pragma unroll
                for (int mi = 0; mi < 2; mi++)
#pragma unroll
                    for (int nj = 0; nj < 4; nj++)
                        MMA_TF32(sacc[mi][nj], af[mi], &bf[nj >> 1][(nj & 1) * 2]);
            }

        // ---- mask, rowsum partials, stash tf32 S (chunked layout) --------
        float pr[2][2] = { {0.f, 0.f}, {0.f, 0.f} };
#pragma unroll
        for (int mi = 0; mi < 2; mi++) {
            int r0  = wm * 32 + mi * 16 + g;
            int swr = (r0 >> 1) & 3;          // same for r0+8
#pragma unroll
            for (int nj = 0; nj < 4; nj++) {
                int col = wn * 32 + nj * 8 + 2 * t;
                float2 m0 = *(const float2*)&mask[mbase + (size_t)(s0 + r0    ) * Ss + t0 + col];
                float2 m1 = *(const float2*)&mask[mbase + (size_t)(s0 + r0 + 8) * Ss + t0 + col];
                float v0 = sacc[mi][nj][0] * m0.x;
                float v1 = sacc[mi][nj][1] * m0.y;
                float v2 = sacc[mi][nj][2] * m1.x;
                float v3 = sacc[mi][nj][3] * m1.y;
                pr[mi][0] += v0 + v1;
                pr[mi][1] += v2 + v3;
                int kb2 = col >> 4, cc = (col >> 2) & 3, lo = col & 3;
                int idx = kb2 * 1024 + r0 * 16 + ((cc ^ swr) << 2) + lo;
                float2 s01 = { to_tf32(v0), to_tf32(v1) };
                float2 s23 = { to_tf32(v2), to_tf32(v3) };
                *(float2*)&Ssm[idx]       = s01;
                *(float2*)&Ssm[idx + 128] = s23;      // +8 rows * 16 floats
            }
        }
#pragma unroll
        for (int mi = 0; mi < 2; mi++)
#pragma unroll
            for (int rr = 0; rr < 2; rr++) {
                float p = pr[mi][rr];
                p += __shfl_xor_sync(0xffffffffu, p, 1);
                p += __shfl_xor_sync(0xffffffffu, p, 2);
                if (t == 0) part[wn * 64 + wm * 32 + mi * 16 + rr * 8 + g] = p;
            }
        __syncthreads();

        if (tid < 64) rsum[tid] += part[tid] + part[64 + tid];

        // ---- O += S * V ---------------------------------------------------
#pragma unroll
        for (int kb = 0; kb < 4; kb++)
#pragma unroll
            for (int ks = 0; ks < 2; ks++) {
                const int ks2 = ks * 2;
                unsigned af[2][4];
#pragma unroll
                for (int mi = 0; mi < 2; mi++)
                    ldsm4(af[mi], sSb + kb * 4096 + a_off[mi] +
                                  (((ks2 + dkA) ^ a_sw[mi]) << 4));
                unsigned bf[4][4];
#pragma unroll
                for (int p = 0; p < 4; p++)
                    ldsm4(bf[p], vSb + kb * 8192 + bv_off[p] +
                                 (((ks2 + dkB) ^ bv_sw[p]) << 4));
#pragma unroll
                for (int mi = 0; mi < 2; mi++)
#pragma unroll
                    for (int nj = 0; nj < 8; nj++)
                        MMA_TF32(oacc[mi][nj], af[mi], &bf[nj >> 1][(nj & 1) * 2]);
            }
        __syncthreads();
    }

    // ---- epilogue: rowsum divide, fused group-RMSnorm + SiLU gate ---------
    float ssq[2][2] = { {0.f, 0.f}, {0.f, 0.f} };
#pragma unroll
    for (int mi = 0; mi < 2; mi++) {
        int r0 = wm * 32 + mi * 16 + g;
        float i0 = 1.f / fmaxf(fabsf(rsum[r0    ]), 1.f);
        float i1 = 1.f / fmaxf(fabsf(rsum[r0 + 8]), 1.f);
#pragma unroll
        for (int nj = 0; nj < 8; nj++) {
            oacc[mi][nj][0] *= i0;  oacc[mi][nj][1] *= i0;
            oacc[mi][nj][2] *= i1;  oacc[mi][nj][3] *= i1;
            ssq[mi][0] += oacc[mi][nj][0] * oacc[mi][nj][0]
                        + oacc[mi][nj][1] * oacc[mi][nj][1];
            ssq[mi][1] += oacc[mi][nj][2] * oacc[mi][nj][2]
                        + oacc[mi][nj][3] * oacc[mi][nj][3];
        }
    }
#pragma unroll
    for (int mi = 0; mi < 2; mi++)
#pragma unroll
        for (int rr = 0; rr < 2; rr++) {
            float p = ssq[mi][rr];
            p += __shfl_xor_sync(0xffffffffu, p, 1);
            p += __shfl_xor_sync(0xffffffffu, p, 2);
            if (t == 0) part[wn * 64 + wm * 32 + mi * 16 + rr * 8 + g] = p;
        }
    __syncthreads();

#pragma unroll
    for (int mi = 0; mi < 2; mi++) {
        int rl = wm * 32 + mi * 16 + g;
        float t0s = part[rl    ] + part[64 + rl    ];
        float t1s = part[rl + 8] + part[64 + rl + 8];
        float rms0 = rsqrtf(t0s * (1.f / 128.f) + 1e-5f);
        float rms1 = rsqrtf(t1s * (1.f / 128.f) + 1e-5f);
#pragma unroll
        for (int nj = 0; nj < 8; nj++) {
            int col = h * HD + wn * 64 + nj * 8 + 2 * t;
            size_t off0 = (size_t)(b * Ss + s0 + rl    ) * VD + col;
            size_t off1 = (size_t)(b * Ss + s0 + rl + 8) * VD + col;
            float2 gv0 = *(const float2*)&gate[off0];
            float2 gv1 = *(const float2*)&gate[off1];
            float2 o0, o1;
            o0.x = to_tf32(oacc[mi][nj][0] * rms0 * gv0.x * (1.f / (1.f + __expf(-gv0.x))));
            o0.y = to_tf32(oacc[mi][nj][1] * rms0 * gv0.y * (1.f / (1.f + __expf(-gv0.y))));
            o1.x = to_tf32(oacc[mi][nj][2] * rms1 * gv1.x * (1.f / (1.f + __expf(-gv1.x))));
            o1.y = to_tf32(oacc[mi][nj][3] * rms1 * gv1.y * (1.f / (1.f + __expf(-gv1.y))));
            *(float2*)&ao[off0] = o0;
            *(float2*)&ao[off1] = o1;
        }
    }
}

// ---------------- launcher -------------------------------------------------
extern "C" void kernel_launch(void* const* d_in, const int* in_sizes, int n_in,
                              void* d_out, int out_size)
{
    const float* x    = (const float*)d_in[0];
    const float* sn   = (const float*)d_in[1];
    const float* cs   = (const float*)d_in[2];
    const float* mask = (const float*)d_in[3];
    const float* Wq   = (const float*)d_in[4];
    const float* Wk   = (const float*)d_in[5];
    const float* Wv   = (const float*)d_in[6];
    const float* Wg   = (const float*)d_in[7];
    const float* Wo   = (const float*)d_in[8];
    float* out = (float*)d_out;

    float *q, *k, *v, *g, *ao, *xr, *wr, *vt;
    cudaGetSymbolAddress((void**)&q,  g_q);
    cudaGetSymbolAddress((void**)&k,  g_k);
    cudaGetSymbolAddress((void**)&v,  g_v);
    cudaGetSymbolAddress((void**)&g,  g_g);
    cudaGetSymbolAddress((void**)&ao, g_ao);
    cudaGetSymbolAddress((void**)&xr, g_xr);
    cudaGetSymbolAddress((void**)&wr, g_wr);
    cudaGetSymbolAddress((void**)&vt, g_vt);

    const int attn_smem = 20672 * (int)sizeof(float);   // 82,688 B
    cudaFuncSetAttribute(attn_tc, cudaFuncAttributeMaxDynamicSharedMemorySize,
                         attn_smem);

    pre_round<<<12288, 256>>>((const float4*)x,  (const float4*)Wq,
                              (const float4*)Wk, (const float4*)Wv,
                              (const float4*)Wg, (const float4*)Wo,
                              (float4*)xr, (float4*)wr);

    proj_qkvg<<<dim3(48, 32), 128>>>(xr, wr, sn, cs, q, k, v, g);

    transpose_v<<<dim3(Ss / 32, HD / 32, Bb * HEADS), dim3(32, 8)>>>(v, vt);

    attn_tc<<<dim3(Ss / 64, Bb * HEADS), 128, attn_smem>>>(q, k, vt, mask, g, ao);

    gemm_out<<<dim3(8, 32), 128>>>(ao, wr + 6 * 1024 * 1024, out);
}

// round 14
// speedup vs baseline: 1.4740x; 1.4740x over previous
#include <cuda_runtime.h>

#define Bb 2
#define Ss 2048
#define Hh 1024
#define HEADS 16
#define KD 64
#define VD 2048
#define HD 128
#define MS (Bb*Ss)   /* 4096 rows */

// ---------------- scratch (device globals; no allocation allowed) ----------
__device__ float g_q [MS*Hh];
__device__ float g_k [MS*Hh];
__device__ float g_v [MS*VD];
__device__ float g_g [MS*VD];
__device__ float g_ao[MS*VD];
__device__ float g_xr[MS*Hh];          // tf32-rounded x
__device__ float g_wr[8*1024*1024];    // tf32-rounded Wq|Wk|Wv|Wg|Wo

// ---------------- helpers --------------------------------------------------
__device__ __forceinline__ float to_tf32(float x) {
    unsigned u;
    asm("cvt.rna.tf32.f32 %0, %1;" : "=r"(u) : "f"(x));
    return __uint_as_float(u);
}

#define MMA_TF32(c, a, b)                                                     \
    asm volatile(                                                             \
        "mma.sync.aligned.m16n8k8.row.col.f32.tf32.tf32.f32 "                 \
        "{%0,%1,%2,%3}, {%4,%5,%6,%7}, {%8,%9}, {%0,%1,%2,%3};"               \
        : "+f"((c)[0]), "+f"((c)[1]), "+f"((c)[2]), "+f"((c)[3])              \
        : "r"((a)[0]), "r"((a)[1]), "r"((a)[2]), "r"((a)[3]),                 \
          "r"((b)[0]), "r"((b)[1]))

__device__ __forceinline__ void ldsm4(unsigned r[4], unsigned addr) {
    asm volatile("ldmatrix.sync.aligned.m8n8.x4.shared.b16 {%0,%1,%2,%3}, [%4];"
                 : "=r"(r[0]), "=r"(r[1]), "=r"(r[2]), "=r"(r[3]) : "r"(addr));
}
__device__ __forceinline__ void cp16(unsigned saddr, const void* gaddr) {
    asm volatile("cp.async.cg.shared.global [%0], [%1], 16;"
                 :: "r"(saddr), "l"(gaddr));
}
#define CP_COMMIT() asm volatile("cp.async.commit_group;")
#define CP_WAIT0()  asm volatile("cp.async.wait_group 0;")
#define CP_WAIT1()  asm volatile("cp.async.wait_group 1;")
#define CP_WAIT2()  asm volatile("cp.async.wait_group 2;")

// ---------------- producer-side tf32 rounding pass --------------------------
__global__ __launch_bounds__(256)
void pre_round(const float4* __restrict__ x,  const float4* __restrict__ wq,
               const float4* __restrict__ wk, const float4* __restrict__ wv,
               const float4* __restrict__ wg, const float4* __restrict__ wo,
               float4* __restrict__ xr, float4* __restrict__ wr)
{
    int i = blockIdx.x * blockDim.x + threadIdx.x;
    const float4* src; float4* dst; int off;
    if (i < 1048576)      { src = x;  dst = xr;            off = i; }
    else if (i < 1310720) { src = wq; dst = wr;            off = i - 1048576; }
    else if (i < 1572864) { src = wk; dst = wr + 262144;   off = i - 1310720; }
    else if (i < 2097152) { src = wv; dst = wr + 524288;   off = i - 1572864; }
    else if (i < 2621440) { src = wg; dst = wr + 1048576;  off = i - 2097152; }
    else                  { src = wo; dst = wr + 1572864;  off = i - 2621440; }
    float4 a = src[off];
    dst[off] = make_float4(to_tf32(a.x), to_tf32(a.y), to_tf32(a.z), to_tf32(a.w));
}

// ============================================================================
// Core 128x128 tf32 GEMM body (proven, unchanged).
// ============================================================================
__device__ __forceinline__ void gemm128_body(
    const float* __restrict__ A, const float* __restrict__ Bm,
    float* __restrict__ C, int N, int K, float alpha,
    int m0, int n0, bool rope, bool outRound,
    const float* __restrict__ sn, const float* __restrict__ cs,
    float* As, float* Bs)
{
    const int tid  = threadIdx.x;
    const int warp = tid >> 5, lane = tid & 31;
    const int g    = lane >> 2, t = lane & 3;
    const int wm   = warp >> 1;
    const int wn   = warp & 1;
    const int row0 = tid >> 2;
    const int k4   = tid & 3;

    float acc[4][8][4];
#pragma unroll
    for (int i = 0; i < 4; i++)
#pragma unroll
        for (int j = 0; j < 8; j++)
#pragma unroll
            for (int r = 0; r < 4; r++) acc[i][j][r] = 0.f;

    const float* Ag = A  + (size_t)(m0 + row0) * K + k4 * 4;
    const float* Bg = Bm + (size_t)(n0 + row0) * K + k4 * 4;
    const size_t rstep = (size_t)32 * K;

    const unsigned aSb = (unsigned)__cvta_generic_to_shared(As);
    const unsigned bSb = (unsigned)__cvta_generic_to_shared(Bs);

    unsigned sA[4], sB[4];
#pragma unroll
    for (int r = 0; r < 4; r++) {
        int rr  = row0 + r * 32;
        int idx = rr * 4 + (k4 ^ ((rr >> 1) & 3));
        sA[r] = aSb + idx * 16;
        sB[r] = bSb + idx * 16;
    }

    const int sel = lane >> 3;
    unsigned a_off[4]; int a_sw[4];
#pragma unroll
    for (int mi = 0; mi < 4; mi++) {
        int mr = wm * 64 + mi * 16 + (sel & 1) * 8 + (lane & 7);
        a_sw[mi]  = (mr >> 1) & 3;
        a_off[mi] = aSb + mr * 64;
    }
    const int dkA = sel >> 1;
    unsigned b_off[4]; int b_sw[4];
#pragma unroll
    for (int p = 0; p < 4; p++) {
        int nr = wn * 64 + p * 16 + (sel >> 1) * 8 + (lane & 7);
        b_sw[p]  = (nr >> 1) & 3;
        b_off[p] = bSb + nr * 64;
    }
    const int dkB = sel & 1;

    const int NIT = K / 16;

#pragma unroll
    for (int st = 0; st < 2; st++) {
        const float* Agn = Ag + st * 16;
        const float* Bgn = Bg + st * 16;
#pragma unroll
        for (int r = 0; r < 4; r++) {
            cp16(sA[r] + st * 8192, Agn + r * rstep);
            cp16(sB[r] + st * 8192, Bgn + r * rstep);
        }
        CP_COMMIT();
    }

    int stage = 0;
    for (int it = 0; it < NIT; ++it) {
        CP_WAIT1();
        __syncthreads();

        const int inext = it + 2;
        if (inext < NIT) {
            const unsigned so = (unsigned)((inext % 3) * 8192);
            const float* Agn = Ag + inext * 16;
            const float* Bgn = Bg + inext * 16;
#pragma unroll
            for (int r = 0; r < 4; r++) {
                cp16(sA[r] + so, Agn + r * rstep);
                cp16(sB[r] + so, Bgn + r * rstep);
            }
        }
        CP_COMMIT();

        const unsigned so = (unsigned)(stage * 8192);
#pragma unroll
        for (int ks = 0; ks < 2; ks++) {
            const int ks2 = ks * 2;
            unsigned af[4][4];
#pragma unroll
            for (int mi = 0; mi < 4; mi++)
                ldsm4(af[mi], a_off[mi] + so + (((ks2 + dkA) ^ a_sw[mi]) << 4));
            unsigned bf[4][4];
#pragma unroll
            for (int p = 0; p < 4; p++)
                ldsm4(bf[p], b_off[p] + so + (((ks2 + dkB) ^ b_sw[p]) << 4));
#pragma unroll
            for (int mi = 0; mi < 4; mi++)
#pragma unroll
                for (int nj = 0; nj < 8; nj++)
                    MMA_TF32(acc[mi][nj], af[mi], &bf[nj >> 1][(nj & 1) * 2]);
        }
        stage = (stage == 2) ? 0 : stage + 1;
    }

#pragma unroll
    for (int mi = 0; mi < 4; mi++) {
        int r0  = m0 + wm * 64 + mi * 16 + g;
        int sA_ = r0 & (Ss - 1);
        int sB_ = (r0 + 8) & (Ss - 1);
#pragma unroll
        for (int nj = 0; nj < 8; nj++) {
            int col = n0 + wn * 64 + nj * 8 + 2 * t;
            float e0 = alpha * acc[mi][nj][0];
            float o0 = alpha * acc[mi][nj][1];
            float e1 = alpha * acc[mi][nj][2];
            float o1 = alpha * acc[mi][nj][3];
            if (rope) {
                int hc = col & 63;
                float2 cA = *(const float2*)&cs[sA_ * KD + hc];
                float2 sAv= *(const float2*)&sn[sA_ * KD + hc];
                float2 cB = *(const float2*)&cs[sB_ * KD + hc];
                float2 sBv= *(const float2*)&sn[sB_ * KD + hc];
                float ne0 = e0 * cA.x - o0 * sAv.x;
                float no0 = o0 * cA.y + e0 * sAv.y;
                float ne1 = e1 * cB.x - o1 * sBv.x;
                float no1 = o1 * cB.y + e1 * sBv.y;
                e0 = ne0; o0 = no0; e1 = ne1; o1 = no1;
            }
            if (outRound) {
                e0 = to_tf32(e0); o0 = to_tf32(o0);
                e1 = to_tf32(e1); o1 = to_tf32(o1);
            }
            float2 w01 = { e0, o0 };
            float2 w23 = { e1, o1 };
            *(float2*)&C[(size_t)r0 * N + col]       = w01;
            *(float2*)&C[(size_t)(r0 + 8) * N + col] = w23;
        }
    }
}

// ---------------- fused Q/K/V/G projections (+rope on q,k) -----------------
__global__ __launch_bounds__(128, 2)
void proj_qkvg(const float* __restrict__ x, const float* __restrict__ wr,
               const float* __restrict__ sn, const float* __restrict__ cs,
               float* __restrict__ q, float* __restrict__ k,
               float* __restrict__ v, float* __restrict__ g)
{
    __shared__ float As[3 * 2048];
    __shared__ float Bs[3 * 2048];
    const int bx = blockIdx.x;
    const float* Bm; float* Cp; int Nloc; float alpha; bool rope, orn; int nb;
    if (bx < 8)       { Bm = wr;           Cp = q; Nloc = 1024; alpha = 1.f;    rope = true;  orn = true;  nb = bx; }
    else if (bx < 16) { Bm = wr + 1048576; Cp = k; Nloc = 1024; alpha = 0.125f; rope = true;  orn = true;  nb = bx - 8; }
    else if (bx < 32) { Bm = wr + 2097152; Cp = v; Nloc = 2048; alpha = 1.f;    rope = false; orn = true;  nb = bx - 16; }
    else              { Bm = wr + 4194304; Cp = g; Nloc = 2048; alpha = 1.f;    rope = false; orn = false; nb = bx - 32; }
    gemm128_body(x, Bm, Cp, Nloc, Hh, alpha, blockIdx.y * 128, nb * 128,
                 rope, orn, sn, cs, As, Bs);
}

// ---------------- output projection ----------------------------------------
__global__ __launch_bounds__(128, 2)
void gemm_out(const float* __restrict__ A, const float* __restrict__ Bm,
              float* __restrict__ C)
{
    __shared__ float As[3 * 2048];
    __shared__ float Bs[3 * 2048];
    gemm128_body(A, Bm, C, Hh, VD, 1.f, blockIdx.y * 128, blockIdx.x * 128,
                 false, false, nullptr, nullptr, As, Bs);
}

// ---------------- retention attention (R11 structure + cp.async overlap) ---
// 256 thr / 8 warps, warp tiles S 32x16, O 32x32 (proven R11 layout).
// K double-buffered: K(tt+1) prefetched during iteration tt.
// V single-buffered: issued after previous O-phase frees Vs, waited just
// before the O-phase (latency hidden behind S MMAs + mask phase).
// Group order: ... K(tt), V(tt), K(tt+1), V(tt+1) ...
#define AST 68
#define VST 136
__global__ __launch_bounds__(256, 2)
void attn_tc(const float* __restrict__ q, const float* __restrict__ k,
             const float* __restrict__ v, const float* __restrict__ mask,
             const float* __restrict__ gate, float* __restrict__ ao)
{
    extern __shared__ float sm[];
    float* Qs   = sm;                    // [64][AST]
    float* Ks0  = Qs  + 64 * AST;        // [64][AST]  K stage 0
    float* Ks1  = Ks0 + 64 * AST;        // [64][AST]  K stage 1
    float* Ssm  = Ks1 + 64 * AST;        // [64][AST]
    float* Vs   = Ssm + 64 * AST;        // [64][VST]
    float* part = Vs  + 64 * VST;        // [4][64]
    float* rsum = part + 256;            // [64]

    const int tid  = threadIdx.x;
    const int warp = tid >> 5, lane = tid & 31;
    const int g    = lane >> 2, t = lane & 3;
    const int wm   = warp >> 2;          // 0..1
    const int wn   = warp & 3;           // 0..3
    const int sb   = blockIdx.x, bh = blockIdx.y;
    const int b    = bh / HEADS, h = bh % HEADS;
    const int s0   = sb * 64;

    const unsigned k0Sb = (unsigned)__cvta_generic_to_shared(Ks0);
    const unsigned k1Sb = (unsigned)__cvta_generic_to_shared(Ks1);
    const unsigned vSb  = (unsigned)__cvta_generic_to_shared(Vs);

    if (tid < 64) rsum[tid] = 0.f;

    // fill-pattern indices (256 threads)
    const int kr  = tid >> 4;            // 0..15 -> row base, 4 rows per l
    const int kc4 = (tid & 15) << 2;     // 0..60
    const int vr  = tid >> 5;            // 0..7
    const int vc4 = (tid & 31) << 2;     // 0..124

    // Q tile (plain loads, once)
#pragma unroll
    for (int l = 0; l < 4; l++) {
        int lin = tid + l * 256, r = lin >> 4, c4 = (lin & 15) << 2;
        *(float4*)&Qs[r * AST + c4] =
            *(const float4*)&q[(size_t)(b * Ss + s0 + r) * Hh + h * KD + c4];
    }

    // prologue: K(0) group, V(0) group
#pragma unroll
    for (int l = 0; l < 4; l++) {
        int r = kr + l * 16;
        cp16(k0Sb + (r * AST + kc4) * 4,
             k + (size_t)(b * Ss + r) * Hh + h * KD + kc4);
    }
    CP_COMMIT();
#pragma unroll
    for (int l = 0; l < 8; l++) {
        int r = vr + l * 8;
        cp16(vSb + (r * VST + vc4) * 4,
             v + (size_t)(b * Ss + r) * VD + h * HD + vc4);
    }
    CP_COMMIT();

    float oacc[2][4][4];
#pragma unroll
    for (int mi = 0; mi < 2; mi++)
#pragma unroll
        for (int nj = 0; nj < 4; nj++)
#pragma unroll
            for (int r = 0; r < 4; r++) oacc[mi][nj][r] = 0.f;

    const size_t mbase = (size_t)h * Ss * Ss;

    for (int tt = 0; tt <= sb; tt++) {
        const int t0 = tt * 64;
        const float* Ks = (tt & 1) ? Ks1 : Ks0;

        // issue K(tt+1) prefetch into the other K stage
        if (tt < sb) {
            const unsigned kd = (tt & 1) ? k0Sb : k1Sb;
            const int tn0 = t0 + 64;
#pragma unroll
            for (int l = 0; l < 4; l++) {
                int r = kr + l * 16;
                cp16(kd + (r * AST + kc4) * 4,
                     k + (size_t)(b * Ss + tn0 + r) * Hh + h * KD + kc4);
            }
            CP_COMMIT();
            CP_WAIT2();              // K(tt) done; [V(tt), K(tt+1)] in flight
        } else {
            CP_WAIT1();              // K(sb) done; [V(sb)] in flight
        }
        __syncthreads();

        // ---- S = Q * K^T : warp tile 32x16 --------------------------------
        float sacc[2][2][4];
#pragma unroll
        for (int mi = 0; mi < 2; mi++)
#pragma unroll
            for (int nj = 0; nj < 2; nj++)
#pragma unroll
                for (int r = 0; r < 4; r++) sacc[mi][nj][r] = 0.f;

#pragma unroll
        for (int ks = 0; ks < 8; ks++) {
            const int kb = ks * 8;
            unsigned af[2][4];
#pragma unroll
            for (int mi = 0; mi < 2; mi++) {
                int mb = wm * 32 + mi * 16 + g;
                af[mi][0] = __float_as_uint(Qs[(mb    ) * AST + kb + t    ]);
                af[mi][1] = __float_as_uint(Qs[(mb + 8) * AST + kb + t    ]);
                af[mi][2] = __float_as_uint(Qs[(mb    ) * AST + kb + t + 4]);
                af[mi][3] = __float_as_uint(Qs[(mb + 8) * AST + kb + t + 4]);
            }
            unsigned bf[2][2];
#pragma unroll
            for (int nj = 0; nj < 2; nj++) {
                int nb = wn * 16 + nj * 8 + g;
                bf[nj][0] = __float_as_uint(Ks[nb * AST + kb + t    ]);
                bf[nj][1] = __float_as_uint(Ks[nb * AST + kb + t + 4]);
            }
#pragma unroll
            for (int mi = 0; mi < 2; mi++)
#pragma unroll
                for (int nj = 0; nj < 2; nj++)
                    MMA_TF32(sacc[mi][nj], af[mi], bf[nj]);
        }

        // ---- mask, rowsum partials, stash tf32 S --------------------------
        float pr[2][2] = { {0.f, 0.f}, {0.f, 0.f} };
#pragma unroll
        for (int mi = 0; mi < 2; mi++) {
            int r0 = wm * 32 + mi * 16 + g;
#pragma unroll
            for (int nj = 0; nj < 2; nj++) {
                int col = wn * 16 + nj * 8 + 2 * t;
                float2 m0 = *(const float2*)&mask[mbase + (size_t)(s0 + r0    ) * Ss + t0 + col];
                float2 m1 = *(const float2*)&mask[mbase + (size_t)(s0 + r0 + 8) * Ss + t0 + col];
                float v0 = sacc[mi][nj][0] * m0.x;
                float v1 = sacc[mi][nj][1] * m0.y;
                float v2 = sacc[mi][nj][2] * m1.x;
                float v3 = sacc[mi][nj][3] * m1.y;
                pr[mi][0] += v0 + v1;
                pr[mi][1] += v2 + v3;
                float2 s01 = { to_tf32(v0), to_tf32(v1) };
                float2 s23 = { to_tf32(v2), to_tf32(v3) };
                *(float2*)&Ssm[(r0    ) * AST + col] = s01;
                *(float2*)&Ssm[(r0 + 8) * AST + col] = s23;
            }
        }
#pragma unroll
        for (int mi = 0; mi < 2; mi++)
#pragma unroll
            for (int rr = 0; rr < 2; rr++) {
                float p = pr[mi][rr];
                p += __shfl_xor_sync(0xffffffffu, p, 1);
                p += __shfl_xor_sync(0xffffffffu, p, 2);
                if (t == 0) part[wn * 64 + wm * 32 + mi * 16 + rr * 8 + g] = p;
            }

        // wait for V(tt) (K(tt+1) may still be in flight)
        if (tt < sb) { CP_WAIT1(); } else { CP_WAIT0(); }
        __syncthreads();

        if (tid < 64)
            rsum[tid] += (part[tid] + part[64 + tid]) + (part[128 + tid] + part[192 + tid]);

        // ---- O += S * V : warp tile 32x32 ---------------------------------
#pragma unroll
        for (int ks = 0; ks < 8; ks++) {
            const int kb = ks * 8;
            unsigned af[2][4];
#pragma unroll
            for (int mi = 0; mi < 2; mi++) {
                int mb = wm * 32 + mi * 16 + g;
                af[mi][0] = __float_as_uint(Ssm[(mb    ) * AST + kb + t    ]);
                af[mi][1] = __float_as_uint(Ssm[(mb + 8) * AST + kb + t    ]);
                af[mi][2] = __float_as_uint(Ssm[(mb    ) * AST + kb + t + 4]);
                af[mi][3] = __float_as_uint(Ssm[(mb + 8) * AST + kb + t + 4]);
            }
            unsigned bf[4][2];
#pragma unroll
            for (int nj = 0; nj < 4; nj++) {
                int nb = wn * 32 + nj * 8 + g;
                bf[nj][0] = __float_as_uint(Vs[(kb + t    ) * VST + nb]);
                bf[nj][1] = __float_as_uint(Vs[(kb + t + 4) * VST + nb]);
            }
#pragma unroll
            for (int mi = 0; mi < 2; mi++)
#pragma unroll
                for (int nj = 0; nj < 4; nj++)
                    MMA_TF32(oacc[mi][nj], af[mi], bf[nj]);
        }
        __syncthreads();   // Vs free

        // issue V(tt+1)
        if (tt < sb) {
            const int tn0 = t0 + 64;
#pragma unroll
            for (int l = 0; l < 8; l++) {
                int r = vr + l * 8;
                cp16(vSb + (r * VST + vc4) * 4,
                     v + (size_t)(b * Ss + tn0 + r) * VD + h * HD + vc4);
            }
            CP_COMMIT();
        }
    }

    // ---- epilogue: rowsum divide, fused group-RMSnorm + SiLU gate ---------
    float ssq[2][2] = { {0.f, 0.f}, {0.f, 0.f} };
#pragma unroll
    for (int mi = 0; mi < 2; mi++) {
        int r0 = wm * 32 + mi * 16 + g;
        float i0 = 1.f / fmaxf(fabsf(rsum[r0    ]), 1.f);
        float i1 = 1.f / fmaxf(fabsf(rsum[r0 + 8]), 1.f);
#pragma unroll
        for (int nj = 0; nj < 4; nj++) {
            oacc[mi][nj][0] *= i0;  oacc[mi][nj][1] *= i0;
            oacc[mi][nj][2] *= i1;  oacc[mi][nj][3] *= i1;
            ssq[mi][0] += oacc[mi][nj][0] * oacc[mi][nj][0]
                        + oacc[mi][nj][1] * oacc[mi][nj][1];
            ssq[mi][1] += oacc[mi][nj][2] * oacc[mi][nj][2]
                        + oacc[mi][nj][3] * oacc[mi][nj][3];
        }
    }
#pragma unroll
    for (int mi = 0; mi < 2; mi++)
#pragma unroll
        for (int rr = 0; rr < 2; rr++) {
            float p = ssq[mi][rr];
            p += __shfl_xor_sync(0xffffffffu, p, 1);
            p += __shfl_xor_sync(0xffffffffu, p, 2);
            if (t == 0) part[wn * 64 + wm * 32 + mi * 16 + rr * 8 + g] = p;
        }
    __syncthreads();

#pragma unroll
    for (int mi = 0; mi < 2; mi++) {
        int rl = wm * 32 + mi * 16 + g;
        float t0s = part[rl    ] + part[64 + rl    ] + part[128 + rl    ] + part[192 + rl    ];
        float t1s = part[rl + 8] + part[64 + rl + 8] + part[128 + rl + 8] + part[192 + rl + 8];
        float rms0 = rsqrtf(t0s * (1.f / 128.f) + 1e-5f);
        float rms1 = rsqrtf(t1s * (1.f / 128.f) + 1e-5f);
#pragma unroll
        for (int nj = 0; nj < 4; nj++) {
            int col = h * HD + wn * 32 + nj * 8 + 2 * t;
            size_t off0 = (size_t)(b * Ss + s0 + rl    ) * VD + col;
            size_t off1 = (size_t)(b * Ss + s0 + rl + 8) * VD + col;
            float2 gv0 = *(const float2*)&gate[off0];
            float2 gv1 = *(const float2*)&gate[off1];
            float2 o0, o1;
            o0.x = to_tf32(oacc[mi][nj][0] * rms0 * gv0.x * (1.f / (1.f + __expf(-gv0.x))));
            o0.y = to_tf32(oacc[mi][nj][1] * rms0 * gv0.y * (1.f / (1.f + __expf(-gv0.y))));
            o1.x = to_tf32(oacc[mi][nj][2] * rms1 * gv1.x * (1.f / (1.f + __expf(-gv1.x))));
            o1.y = to_tf32(oacc[mi][nj][3] * rms1 * gv1.y * (1.f / (1.f + __expf(-gv1.y))));
            *(float2*)&ao[off0] = o0;
            *(float2*)&ao[off1] = o1;
        }
    }
}

// ---------------- launcher -------------------------------------------------
extern "C" void kernel_launch(void* const* d_in, const int* in_sizes, int n_in,
                              void* d_out, int out_size)
{
    const float* x    = (const float*)d_in[0];
    const float* sn   = (const float*)d_in[1];
    const float* cs   = (const float*)d_in[2];
    const float* mask = (const float*)d_in[3];
    const float* Wq   = (const float*)d_in[4];
    const float* Wk   = (const float*)d_in[5];
    const float* Wv   = (const float*)d_in[6];
    const float* Wg   = (const float*)d_in[7];
    const float* Wo   = (const float*)d_in[8];
    float* out = (float*)d_out;

    float *q, *k, *v, *g, *ao, *xr, *wr;
    cudaGetSymbolAddress((void**)&q,  g_q);
    cudaGetSymbolAddress((void**)&k,  g_k);
    cudaGetSymbolAddress((void**)&v,  g_v);
    cudaGetSymbolAddress((void**)&g,  g_g);
    cudaGetSymbolAddress((void**)&ao, g_ao);
    cudaGetSymbolAddress((void**)&xr, g_xr);
    cudaGetSymbolAddress((void**)&wr, g_wr);

    const int attn_smem = (4 * 64 * AST + 64 * VST + 256 + 64) * (int)sizeof(float);
    cudaFuncSetAttribute(attn_tc, cudaFuncAttributeMaxDynamicSharedMemorySize,
                         attn_smem);

    pre_round<<<12288, 256>>>((const float4*)x,  (const float4*)Wq,
                              (const float4*)Wk, (const float4*)Wv,
                              (const float4*)Wg, (const float4*)Wo,
                              (float4*)xr, (float4*)wr);

    proj_qkvg<<<dim3(48, 32), 128>>>(xr, wr, sn, cs, q, k, v, g);

    attn_tc<<<dim3(Ss / 64, Bb * HEADS), 256, attn_smem>>>(q, k, v, mask, g, ao);

    gemm_out<<<dim3(8, 32), 128>>>(ao, wr + 6 * 1024 * 1024, out);
}

// round 15
// speedup vs baseline: 1.5746x; 1.0683x over previous
#include <cuda_runtime.h>

#define Bb 2
#define Ss 2048
#define Hh 1024
#define HEADS 16
#define KD 64
#define VD 2048
#define HD 128
#define MS (Bb*Ss)   /* 4096 rows */

// ---------------- scratch (device globals; no allocation allowed) ----------
__device__ float g_q [MS*Hh];
__device__ float g_k [MS*Hh];
__device__ float g_v [MS*VD];
__device__ float g_g [MS*VD];
__device__ float g_ao[MS*VD];
__device__ float g_xr[MS*Hh];          // tf32-rounded x
__device__ float g_wr[8*1024*1024];    // tf32-rounded Wq|Wk|Wv|Wg|Wo
__device__ float g_tab[HEADS*Ss];      // per-head decay table: mask[h][d][0]

// ---------------- helpers --------------------------------------------------
__device__ __forceinline__ float to_tf32(float x) {
    unsigned u;
    asm("cvt.rna.tf32.f32 %0, %1;" : "=r"(u) : "f"(x));
    return __uint_as_float(u);
}

#define MMA_TF32(c, a, b)                                                     \
    asm volatile(                                                             \
        "mma.sync.aligned.m16n8k8.row.col.f32.tf32.tf32.f32 "                 \
        "{%0,%1,%2,%3}, {%4,%5,%6,%7}, {%8,%9}, {%0,%1,%2,%3};"               \
        : "+f"((c)[0]), "+f"((c)[1]), "+f"((c)[2]), "+f"((c)[3])              \
        : "r"((a)[0]), "r"((a)[1]), "r"((a)[2]), "r"((a)[3]),                 \
          "r"((b)[0]), "r"((b)[1]))

__device__ __forceinline__ void ldsm4(unsigned r[4], unsigned addr) {
    asm volatile("ldmatrix.sync.aligned.m8n8.x4.shared.b16 {%0,%1,%2,%3}, [%4];"
                 : "=r"(r[0]), "=r"(r[1]), "=r"(r[2]), "=r"(r[3]) : "r"(addr));
}
__device__ __forceinline__ void cp16(unsigned saddr, const void* gaddr) {
    asm volatile("cp.async.cg.shared.global [%0], [%1], 16;"
                 :: "r"(saddr), "l"(gaddr));
}
#define CP_COMMIT() asm volatile("cp.async.commit_group;")
#define CP_WAIT0()  asm volatile("cp.async.wait_group 0;")
#define CP_WAIT1()  asm volatile("cp.async.wait_group 1;")
#define CP_WAIT2()  asm volatile("cp.async.wait_group 2;")

// ---------------- producer-side tf32 rounding pass --------------------------
__global__ __launch_bounds__(256)
void pre_round(const float4* __restrict__ x,  const float4* __restrict__ wq,
               const float4* __restrict__ wk, const float4* __restrict__ wv,
               const float4* __restrict__ wg, const float4* __restrict__ wo,
               float4* __restrict__ xr, float4* __restrict__ wr)
{
    int i = blockIdx.x * blockDim.x + threadIdx.x;
    const float4* src; float4* dst; int off;
    if (i < 1048576)      { src = x;  dst = xr;            off = i; }
    else if (i < 1310720) { src = wq; dst = wr;            off = i - 1048576; }
    else if (i < 1572864) { src = wk; dst = wr + 262144;   off = i - 1310720; }
    else if (i < 2097152) { src = wv; dst = wr + 524288;   off = i - 1572864; }
    else if (i < 2621440) { src = wg; dst = wr + 1048576;  off = i - 2097152; }
    else                  { src = wo; dst = wr + 1572864;  off = i - 2621440; }
    float4 a = src[off];
    dst[off] = make_float4(to_tf32(a.x), to_tf32(a.y), to_tf32(a.z), to_tf32(a.w));
}

// ---------------- decay table extraction: tab[h][d] = mask[h][d][0] --------
// Bitwise identical to the full mask: mask[h][i][j] = exp(logd_h*(i-j)) and
// (i-j) is exactly representable, so mask[h][i][j] == mask[h][i-j][0].
__global__ __launch_bounds__(256)
void tab_extract(const float* __restrict__ mask, float* __restrict__ tab)
{
    int i = blockIdx.x * blockDim.x + threadIdx.x;     // 32768
    int h = i >> 11, d = i & 2047;
    tab[i] = mask[(size_t)h * Ss * Ss + (size_t)d * Ss];
}

// ============================================================================
// Core 128x128 tf32 GEMM body (proven, unchanged).
// ============================================================================
__device__ __forceinline__ void gemm128_body(
    const float* __restrict__ A, const float* __restrict__ Bm,
    float* __restrict__ C, int N, int K, float alpha,
    int m0, int n0, bool rope, bool outRound,
    const float* __restrict__ sn, const float* __restrict__ cs,
    float* As, float* Bs)
{
    const int tid  = threadIdx.x;
    const int warp = tid >> 5, lane = tid & 31;
    const int g    = lane >> 2, t = lane & 3;
    const int wm   = warp >> 1;
    const int wn   = warp & 1;
    const int row0 = tid >> 2;
    const int k4   = tid & 3;

    float acc[4][8][4];
#pragma unroll
    for (int i = 0; i < 4; i++)
#pragma unroll
        for (int j = 0; j < 8; j++)
#pragma unroll
            for (int r = 0; r < 4; r++) acc[i][j][r] = 0.f;

    const float* Ag = A  + (size_t)(m0 + row0) * K + k4 * 4;
    const float* Bg = Bm + (size_t)(n0 + row0) * K + k4 * 4;
    const size_t rstep = (size_t)32 * K;

    const unsigned aSb = (unsigned)__cvta_generic_to_shared(As);
    const unsigned bSb = (unsigned)__cvta_generic_to_shared(Bs);

    unsigned sA[4], sB[4];
#pragma unroll
    for (int r = 0; r < 4; r++) {
        int rr  = row0 + r * 32;
        int idx = rr * 4 + (k4 ^ ((rr >> 1) & 3));
        sA[r] = aSb + idx * 16;
        sB[r] = bSb + idx * 16;
    }

    const int sel = lane >> 3;
    unsigned a_off[4]; int a_sw[4];
#pragma unroll
    for (int mi = 0; mi < 4; mi++) {
        int mr = wm * 64 + mi * 16 + (sel & 1) * 8 + (lane & 7);
        a_sw[mi]  = (mr >> 1) & 3;
        a_off[mi] = aSb + mr * 64;
    }
    const int dkA = sel >> 1;
    unsigned b_off[4]; int b_sw[4];
#pragma unroll
    for (int p = 0; p < 4; p++) {
        int nr = wn * 64 + p * 16 + (sel >> 1) * 8 + (lane & 7);
        b_sw[p]  = (nr >> 1) & 3;
        b_off[p] = bSb + nr * 64;
    }
    const int dkB = sel & 1;

    const int NIT = K / 16;

#pragma unroll
    for (int st = 0; st < 2; st++) {
        const float* Agn = Ag + st * 16;
        const float* Bgn = Bg + st * 16;
#pragma unroll
        for (int r = 0; r < 4; r++) {
            cp16(sA[r] + st * 8192, Agn + r * rstep);
            cp16(sB[r] + st * 8192, Bgn + r * rstep);
        }
        CP_COMMIT();
    }

    int stage = 0;
    for (int it = 0; it < NIT; ++it) {
        CP_WAIT1();
        __syncthreads();

        const int inext = it + 2;
        if (inext < NIT) {
            const unsigned so = (unsigned)((inext % 3) * 8192);
            const float* Agn = Ag + inext * 16;
            const float* Bgn = Bg + inext * 16;
#pragma unroll
            for (int r = 0; r < 4; r++) {
                cp16(sA[r] + so, Agn + r * rstep);
                cp16(sB[r] + so, Bgn + r * rstep);
            }
        }
        CP_COMMIT();

        const unsigned so = (unsigned)(stage * 8192);
#pragma unroll
        for (int ks = 0; ks < 2; ks++) {
            const int ks2 = ks * 2;
            unsigned af[4][4];
#pragma unroll
            for (int mi = 0; mi < 4; mi++)
                ldsm4(af[mi], a_off[mi] + so + (((ks2 + dkA) ^ a_sw[mi]) << 4));
            unsigned bf[4][4];
#pragma unroll
            for (int p = 0; p < 4; p++)
                ldsm4(bf[p], b_off[p] + so + (((ks2 + dkB) ^ b_sw[p]) << 4));
#pragma unroll
            for (int mi = 0; mi < 4; mi++)
#pragma unroll
                for (int nj = 0; nj < 8; nj++)
                    MMA_TF32(acc[mi][nj], af[mi], &bf[nj >> 1][(nj & 1) * 2]);
        }
        stage = (stage == 2) ? 0 : stage + 1;
    }

#pragma unroll
    for (int mi = 0; mi < 4; mi++) {
        int r0  = m0 + wm * 64 + mi * 16 + g;
        int sA_ = r0 & (Ss - 1);
        int sB_ = (r0 + 8) & (Ss - 1);
#pragma unroll
        for (int nj = 0; nj < 8; nj++) {
            int col = n0 + wn * 64 + nj * 8 + 2 * t;
            float e0 = alpha * acc[mi][nj][0];
            float o0 = alpha * acc[mi][nj][1];
            float e1 = alpha * acc[mi][nj][2];
            float o1 = alpha * acc[mi][nj][3];
            if (rope) {
                int hc = col & 63;
                float2 cA = *(const float2*)&cs[sA_ * KD + hc];
                float2 sAv= *(const float2*)&sn[sA_ * KD + hc];
                float2 cB = *(const float2*)&cs[sB_ * KD + hc];
                float2 sBv= *(const float2*)&sn[sB_ * KD + hc];
                float ne0 = e0 * cA.x - o0 * sAv.x;
                float no0 = o0 * cA.y + e0 * sAv.y;
                float ne1 = e1 * cB.x - o1 * sBv.x;
                float no1 = o1 * cB.y + e1 * sBv.y;
                e0 = ne0; o0 = no0; e1 = ne1; o1 = no1;
            }
            if (outRound) {
                e0 = to_tf32(e0); o0 = to_tf32(o0);
                e1 = to_tf32(e1); o1 = to_tf32(o1);
            }
            float2 w01 = { e0, o0 };
            float2 w23 = { e1, o1 };
            *(float2*)&C[(size_t)r0 * N + col]       = w01;
            *(float2*)&C[(size_t)(r0 + 8) * N + col] = w23;
        }
    }
}

// ---------------- fused Q/K/V/G projections (+rope on q,k) -----------------
__global__ __launch_bounds__(128, 2)
void proj_qkvg(const float* __restrict__ x, const float* __restrict__ wr,
               const float* __restrict__ sn, const float* __restrict__ cs,
               float* __restrict__ q, float* __restrict__ k,
               float* __restrict__ v, float* __restrict__ g)
{
    __shared__ float As[3 * 2048];
    __shared__ float Bs[3 * 2048];
    const int bx = blockIdx.x;
    const float* Bm; float* Cp; int Nloc; float alpha; bool rope, orn; int nb;
    if (bx < 8)       { Bm = wr;           Cp = q; Nloc = 1024; alpha = 1.f;    rope = true;  orn = true;  nb = bx; }
    else if (bx < 16) { Bm = wr + 1048576; Cp = k; Nloc = 1024; alpha = 0.125f; rope = true;  orn = true;  nb = bx - 8; }
    else if (bx < 32) { Bm = wr + 2097152; Cp = v; Nloc = 2048; alpha = 1.f;    rope = false; orn = true;  nb = bx - 16; }
    else              { Bm = wr + 4194304; Cp = g; Nloc = 2048; alpha = 1.f;    rope = false; orn = false; nb = bx - 32; }
    gemm128_body(x, Bm, Cp, Nloc, Hh, alpha, blockIdx.y * 128, nb * 128,
                 rope, orn, sn, cs, As, Bs);
}

// ---------------- output projection ----------------------------------------
__global__ __launch_bounds__(128, 2)
void gemm_out(const float* __restrict__ A, const float* __restrict__ Bm,
              float* __restrict__ C)
{
    __shared__ float As[3 * 2048];
    __shared__ float Bs[3 * 2048];
    gemm128_body(A, Bm, C, Hh, VD, 1.f, blockIdx.y * 128, blockIdx.x * 128,
                 false, false, nullptr, nullptr, As, Bs);
}

// ---------------- retention attention (R13 + smem decay table) -------------
// 256 thr / 8 warps, warp tiles S 32x16, O 32x32.
// K double-buffered, V single-buffered (cp.async overlap, proven R13).
// Mask replaced by per-tile 128-entry decay window in smem (bitwise equal).
#define AST 68
#define VST 136
__global__ __launch_bounds__(256, 2)
void attn_tc(const float* __restrict__ q, const float* __restrict__ k,
             const float* __restrict__ v, const float* __restrict__ tab,
             const float* __restrict__ gate, float* __restrict__ ao)
{
    extern __shared__ float sm[];
    float* Qs   = sm;                    // [64][AST]
    float* Ks0  = Qs  + 64 * AST;        // [64][AST]  K stage 0
    float* Ks1  = Ks0 + 64 * AST;        // [64][AST]  K stage 1
    float* Ssm  = Ks1 + 64 * AST;        // [64][AST]
    float* Vs   = Ssm + 64 * AST;        // [64][VST]
    float* part = Vs  + 64 * VST;        // [4][64]
    float* rsum = part + 256;            // [64]
    float* tabs = rsum + 64;             // [128] decay window

    const int tid  = threadIdx.x;
    const int warp = tid >> 5, lane = tid & 31;
    const int g    = lane >> 2, t = lane & 3;
    const int wm   = warp >> 2;          // 0..1
    const int wn   = warp & 3;           // 0..3
    const int sb   = blockIdx.x, bh = blockIdx.y;
    const int b    = bh / HEADS, h = bh % HEADS;
    const int s0   = sb * 64;

    const unsigned k0Sb = (unsigned)__cvta_generic_to_shared(Ks0);
    const unsigned k1Sb = (unsigned)__cvta_generic_to_shared(Ks1);
    const unsigned vSb  = (unsigned)__cvta_generic_to_shared(Vs);

    if (tid < 64) rsum[tid] = 0.f;

    // fill-pattern indices (256 threads)
    const int kr  = tid >> 4;            // 0..15
    const int kc4 = (tid & 15) << 2;     // 0..60
    const int vr  = tid >> 5;            // 0..7
    const int vc4 = (tid & 31) << 2;     // 0..124

    // Q tile (plain loads, once)
#pragma unroll
    for (int l = 0; l < 4; l++) {
        int lin = tid + l * 256, r = lin >> 4, c4 = (lin & 15) << 2;
        *(float4*)&Qs[r * AST + c4] =
            *(const float4*)&q[(size_t)(b * Ss + s0 + r) * Hh + h * KD + c4];
    }

    // prologue: K(0) group, V(0) group
#pragma unroll
    for (int l = 0; l < 4; l++) {
        int r = kr + l * 16;
        cp16(k0Sb + (r * AST + kc4) * 4,
             k + (size_t)(b * Ss + r) * Hh + h * KD + kc4);
    }
    CP_COMMIT();
#pragma unroll
    for (int l = 0; l < 8; l++) {
        int r = vr + l * 8;
        cp16(vSb + (r * VST + vc4) * 4,
             v + (size_t)(b * Ss + r) * VD + h * HD + vc4);
    }
    CP_COMMIT();

    float oacc[2][4][4];
#pragma unroll
    for (int mi = 0; mi < 2; mi++)
#pragma unroll
        for (int nj = 0; nj < 4; nj++)
#pragma unroll
            for (int r = 0; r < 4; r++) oacc[mi][nj][r] = 0.f;

    for (int tt = 0; tt <= sb; tt++) {
        const int t0 = tt * 64;
        const float* Ks = (tt & 1) ? Ks1 : Ks0;

        // fill decay window for this tile: diff range [s0-t0-64, s0-t0+63]
        if (tid < 128) {
            int d = (s0 - t0 - 64) + tid;
            tabs[tid] = (d >= 0) ? tab[h * Ss + d] : 0.f;
        }

        // issue K(tt+1) prefetch into the other K stage
        if (tt < sb) {
            const unsigned kd = (tt & 1) ? k0Sb : k1Sb;
            const int tn0 = t0 + 64;
#pragma unroll
            for (int l = 0; l < 4; l++) {
                int r = kr + l * 16;
                cp16(kd + (r * AST + kc4) * 4,
                     k + (size_t)(b * Ss + tn0 + r) * Hh + h * KD + kc4);
            }
            CP_COMMIT();
            CP_WAIT2();              // K(tt) done; [V(tt), K(tt+1)] in flight
        } else {
            CP_WAIT1();              // K(sb) done; [V(sb)] in flight
        }
        __syncthreads();

        // ---- S = Q * K^T : warp tile 32x16 --------------------------------
        float sacc[2][2][4];
#pragma unroll
        for (int mi = 0; mi < 2; mi++)
#pragma unroll
            for (int nj = 0; nj < 2; nj++)
#pragma unroll
                for (int r = 0; r < 4; r++) sacc[mi][nj][r] = 0.f;

#pragma unroll
        for (int ks = 0; ks < 8; ks++) {
            const int kb = ks * 8;
            unsigned af[2][4];
#pragma unroll
            for (int mi = 0; mi < 2; mi++) {
                int mb = wm * 32 + mi * 16 + g;
                af[mi][0] = __float_as_uint(Qs[(mb    ) * AST + kb + t    ]);
                af[mi][1] = __float_as_uint(Qs[(mb + 8) * AST + kb + t    ]);
                af[mi][2] = __float_as_uint(Qs[(mb    ) * AST + kb + t + 4]);
                af[mi][3] = __float_as_uint(Qs[(mb + 8) * AST + kb + t + 4]);
            }
            unsigned bf[2][2];
#pragma unroll
            for (int nj = 0; nj < 2; nj++) {
                int nb = wn * 16 + nj * 8 + g;
                bf[nj][0] = __float_as_uint(Ks[nb * AST + kb + t    ]);
                bf[nj][1] = __float_as_uint(Ks[nb * AST + kb + t + 4]);
            }
#pragma unroll
            for (int mi = 0; mi < 2; mi++)
#pragma unroll
                for (int nj = 0; nj < 2; nj++)
                    MMA_TF32(sacc[mi][nj], af[mi], bf[nj]);
        }

        // ---- mask (smem table), rowsum partials, stash tf32 S -------------
        float pr[2][2] = { {0.f, 0.f}, {0.f, 0.f} };
#pragma unroll
        for (int mi = 0; mi < 2; mi++) {
            int r0 = wm * 32 + mi * 16 + g;
#pragma unroll
            for (int nj = 0; nj < 2; nj++) {
                int col = wn * 16 + nj * 8 + 2 * t;
                int ix  = r0 - col + 64;
                float v0 = sacc[mi][nj][0] * tabs[ix];
                float v1 = sacc[mi][nj][1] * tabs[ix - 1];
                float v2 = sacc[mi][nj][2] * tabs[ix + 8];
                float v3 = sacc[mi][nj][3] * tabs[ix + 7];
                pr[mi][0] += v0 + v1;
                pr[mi][1] += v2 + v3;
                float2 s01 = { to_tf32(v0), to_tf32(v1) };
                float2 s23 = { to_tf32(v2), to_tf32(v3) };
                *(float2*)&Ssm[(r0    ) * AST + col] = s01;
                *(float2*)&Ssm[(r0 + 8) * AST + col] = s23;
            }
        }
#pragma unroll
        for (int mi = 0; mi < 2; mi++)
#pragma unroll
            for (int rr = 0; rr < 2; rr++) {
                float p = pr[mi][rr];
                p += __shfl_xor_sync(0xffffffffu, p, 1);
                p += __shfl_xor_sync(0xffffffffu, p, 2);
                if (t == 0) part[wn * 64 + wm * 32 + mi * 16 + rr * 8 + g] = p;
            }

        // wait for V(tt) (K(tt+1) may still be in flight)
        if (tt < sb) { CP_WAIT1(); } else { CP_WAIT0(); }
        __syncthreads();

        if (tid < 64)
            rsum[tid] += (part[tid] + part[64 + tid]) + (part[128 + tid] + part[192 + tid]);

        // ---- O += S * V : warp tile 32x32 ---------------------------------
#pragma unroll
        for (int ks = 0; ks < 8; ks++) {
            const int kb = ks * 8;
            unsigned af[2][4];
#pragma unroll
            for (int mi = 0; mi < 2; mi++) {
                int mb = wm * 32 + mi * 16 + g;
                af[mi][0] = __float_as_uint(Ssm[(mb    ) * AST + kb + t    ]);
                af[mi][1] = __float_as_uint(Ssm[(mb + 8) * AST + kb + t    ]);
                af[mi][2] = __float_as_uint(Ssm[(mb    ) * AST + kb + t + 4]);
                af[mi][3] = __float_as_uint(Ssm[(mb + 8) * AST + kb + t + 4]);
            }
            unsigned bf[4][2];
#pragma unroll
            for (int nj = 0; nj < 4; nj++) {
                int nb = wn * 32 + nj * 8 + g;
                bf[nj][0] = __float_as_uint(Vs[(kb + t    ) * VST + nb]);
                bf[nj][1] = __float_as_uint(Vs[(kb + t + 4) * VST + nb]);
            }
#pragma unroll
            for (int mi = 0; mi < 2; mi++)
#pragma unroll
                for (int nj = 0; nj < 4; nj++)
                    MMA_TF32(oacc[mi][nj], af[mi], bf[nj]);
        }
        __syncthreads();   // Vs free

        // issue V(tt+1)
        if (tt < sb) {
            const int tn0 = t0 + 64;
#pragma unroll
            for (int l = 0; l < 8; l++) {
                int r = vr + l * 8;
                cp16(vSb + (r * VST + vc4) * 4,
                     v + (size_t)(b * Ss + tn0 + r) * VD + h * HD + vc4);
            }
            CP_COMMIT();
        }
    }

    // ---- epilogue: rowsum divide, fused group-RMSnorm + SiLU gate ---------
    float ssq[2][2] = { {0.f, 0.f}, {0.f, 0.f} };
#pragma unroll
    for (int mi = 0; mi < 2; mi++) {
        int r0 = wm * 32 + mi * 16 + g;
        float i0 = 1.f / fmaxf(fabsf(rsum[r0    ]), 1.f);
        float i1 = 1.f / fmaxf(fabsf(rsum[r0 + 8]), 1.f);
#pragma unroll
        for (int nj = 0; nj < 4; nj++) {
            oacc[mi][nj][0] *= i0;  oacc[mi][nj][1] *= i0;
            oacc[mi][nj][2] *= i1;  oacc[mi][nj][3] *= i1;
            ssq[mi][0] += oacc[mi][nj][0] * oacc[mi][nj][0]
                        + oacc[mi][nj][1] * oacc[mi][nj][1];
            ssq[mi][1] += oacc[mi][nj][2] * oacc[mi][nj][2]
                        + oacc[mi][nj][3] * oacc[mi][nj][3];
        }
    }
#pragma unroll
    for (int mi = 0; mi < 2; mi++)
#pragma unroll
        for (int rr = 0; rr < 2; rr++) {
            float p = ssq[mi][rr];
            p += __shfl_xor_sync(0xffffffffu, p, 1);
            p += __shfl_xor_sync(0xffffffffu, p, 2);
            if (t == 0) part[wn * 64 + wm * 32 + mi * 16 + rr * 8 + g] = p;
        }
    __syncthreads();

#pragma unroll
    for (int mi = 0; mi < 2; mi++) {
        int rl = wm * 32 + mi * 16 + g;
        float t0s = part[rl    ] + part[64 + rl    ] + part[128 + rl    ] + part[192 + rl    ];
        float t1s = part[rl + 8] + part[64 + rl + 8] + part[128 + rl + 8] + part[192 + rl + 8];
        float rms0 = rsqrtf(t0s * (1.f / 128.f) + 1e-5f);
        float rms1 = rsqrtf(t1s * (1.f / 128.f) + 1e-5f);
#pragma unroll
        for (int nj = 0; nj < 4; nj++) {
            int col = h * HD + wn * 32 + nj * 8 + 2 * t;
            size_t off0 = (size_t)(b * Ss + s0 + rl    ) * VD + col;
            size_t off1 = (size_t)(b * Ss + s0 + rl + 8) * VD + col;
            float2 gv0 = *(const float2*)&gate[off0];
            float2 gv1 = *(const float2*)&gate[off1];
            float2 o0, o1;
            o0.x = to_tf32(oacc[mi][nj][0] * rms0 * gv0.x * (1.f / (1.f + __expf(-gv0.x))));
            o0.y = to_tf32(oacc[mi][nj][1] * rms0 * gv0.y * (1.f / (1.f + __expf(-gv0.y))));
            o1.x = to_tf32(oacc[mi][nj][2] * rms1 * gv1.x * (1.f / (1.f + __expf(-gv1.x))));
            o1.y = to_tf32(oacc[mi][nj][3] * rms1 * gv1.y * (1.f / (1.f + __expf(-gv1.y))));
            *(float2*)&ao[off0] = o0;
            *(float2*)&ao[off1] = o1;
        }
    }
}

// ---------------- launcher -------------------------------------------------
extern "C" void kernel_launch(void* const* d_in, const int* in_sizes, int n_in,
                              void* d_out, int out_size)
{
    const float* x    = (const float*)d_in[0];
    const float* sn   = (const float*)d_in[1];
    const float* cs   = (const float*)d_in[2];
    const float* mask = (const float*)d_in[3];
    const float* Wq   = (const float*)d_in[4];
    const float* Wk   = (const float*)d_in[5];
    const float* Wv   = (const float*)d_in[6];
    const float* Wg   = (const float*)d_in[7];
    const float* Wo   = (const float*)d_in[8];
    float* out = (float*)d_out;

    float *q, *k, *v, *g, *ao, *xr, *wr, *tb;
    cudaGetSymbolAddress((void**)&q,  g_q);
    cudaGetSymbolAddress((void**)&k,  g_k);
    cudaGetSymbolAddress((void**)&v,  g_v);
    cudaGetSymbolAddress((void**)&g,  g_g);
    cudaGetSymbolAddress((void**)&ao, g_ao);
    cudaGetSymbolAddress((void**)&xr, g_xr);
    cudaGetSymbolAddress((void**)&wr, g_wr);
    cudaGetSymbolAddress((void**)&tb, g_tab);

    const int attn_smem = (4 * 64 * AST + 64 * VST + 256 + 64 + 128) * (int)sizeof(float);
    cudaFuncSetAttribute(attn_tc, cudaFuncAttributeMaxDynamicSharedMemorySize,
                         attn_smem);

    pre_round<<<12288, 256>>>((const float4*)x,  (const float4*)Wq,
                              (const float4*)Wk, (const float4*)Wv,
                              (const float4*)Wg, (const float4*)Wo,
                              (float4*)xr, (float4*)wr);

    tab_extract<<<128, 256>>>(mask, tb);

    proj_qkvg<<<dim3(48, 32), 128>>>(xr, wr, sn, cs, q, k, v, g);

    attn_tc<<<dim3(Ss / 64, Bb * HEADS), 256, attn_smem>>>(q, k, v, tb, g, ao);

    gemm_out<<<dim3(8, 32), 128>>>(ao, wr + 6 * 1024 * 1024, out);
}